// round 3
// baseline (speedup 1.0000x reference)
#include <cuda_runtime.h>

// SampleDepthwise deformable depthwise conv — register-weight version.
// B=8, C=256, H=W=96, K=3, S=4, PAD=1.
//
// Layout: warp lanes = channels (2 per lane). Per-pixel bilinear data
// (coefs + quad index) is warp-uniform -> the 2x2 weight quad is selected
// from per-lane REGISTER weight tables via a warp-uniform 25-case switch.
// This removes the scattered LDS.128 quad gather that made the previous
// kernel L1-wavefront bound (80% L1 SOL, ~42M wavefronts).
//
// x is staged through a 3-row smem ring in [w][channel] layout (coalesced
// LDG in, lane-contiguous LDS out); out staged through smem and written
// coalesced. Coefs are computed cooperatively once per (pixel, tap).

#define BN 8
#define CN 256
#define HN 96
#define WN 96
#define HW (HN * WN)

constexpr int CPB = 64;          // channels per block (2 per lane)
constexpr int WPB = 32;          // pixel columns per block
constexpr int RPB = 24;          // rows per block
constexpr int NTH = 256;         // 8 warps
constexpr int XW  = WPB + 2;     // 34 staged x columns (w-1 .. w+32)
constexpr int XC  = CPB + 2;     // padded channel stride (floats)

struct WPair { float2 v[16]; };

// Warp-uniform quad blend: qi = qy*5+qx encodes clamp(y0,-1,3)+1 etc.
// Row pair (r0,r1) = (clip(y0,0,3), clip(y0+1,0,3)); invalid corners have
// zero coefs, so clamped indices are harmless.
__device__ __forceinline__ float2 qblend(int qi, const WPair& wp, float4 cf) {
    float2 g;
    switch (qi) {
#define QB(QY, QX)                                                         \
    case (QY) * 5 + (QX): {                                                \
        constexpr int r0 = (QY) > 0 ? (QY) - 1 : 0;                        \
        constexpr int r1 = (QY) < 4 ? (QY) : 3;                            \
        constexpr int s0 = (QX) > 0 ? (QX) - 1 : 0;                        \
        constexpr int s1 = (QX) < 4 ? (QX) : 3;                            \
        const float2 a  = wp.v[r0 * 4 + s0];                               \
        const float2 bq = wp.v[r0 * 4 + s1];                               \
        const float2 c_ = wp.v[r1 * 4 + s0];                               \
        const float2 d  = wp.v[r1 * 4 + s1];                               \
        g.x = fmaf(cf.x, a.x, fmaf(cf.y, bq.x, fmaf(cf.z, c_.x, cf.w * d.x))); \
        g.y = fmaf(cf.x, a.y, fmaf(cf.y, bq.y, fmaf(cf.z, c_.y, cf.w * d.y))); \
        break; }
    QB(0,0) QB(0,1) QB(0,2) QB(0,3) QB(0,4)
    QB(1,0) QB(1,1) QB(1,2) QB(1,3) QB(1,4)
    QB(2,0) QB(2,1) QB(2,2) QB(2,3) QB(2,4)
    QB(3,0) QB(3,1) QB(3,2) QB(3,3) QB(3,4)
    QB(4,0) QB(4,1) QB(4,2) QB(4,3) QB(4,4)
#undef QB
    default:
        g = make_float2(0.f, 0.f);
    }
    return g;
}

__global__ __launch_bounds__(NTH, 3)
void sdw_kernel(const float* __restrict__ x,
                const float* __restrict__ rot,
                const float* __restrict__ wgt,
                float* __restrict__ out)
{
    __shared__ __align__(16) float  sx[3][XW][XC];  // 26928 B x ring
    __shared__ __align__(16) float4 scf[WPB][9];    // 4608 B coefs
    __shared__              int     sqi[WPB][9];    // 1152 B quad idx
    __shared__ __align__(16) float  so[WPB][XC];    // 8448 B out staging

    const int tid  = threadIdx.x;
    const int lane = tid & 31;
    const int warp = tid >> 5;

    const int b     = blockIdx.y;
    const int c0    = blockIdx.z * CPB;
    const int colc  = blockIdx.x % 3;
    const int rowc  = blockIdx.x / 3;
    const int wbase = colc * WPB;
    const int r0    = rowc * RPB;

    // ---- per-lane register weights: channels c0+2*lane, c0+2*lane+1 ----
    WPair wp;
    {
        const float4* wa = reinterpret_cast<const float4*>(wgt + (c0 + 2 * lane) * 16);
        const float4* wb = reinterpret_cast<const float4*>(wgt + (c0 + 2 * lane + 1) * 16);
        #pragma unroll
        for (int i = 0; i < 4; i++) {
            const float4 a = __ldg(wa + i);
            const float4 e = __ldg(wb + i);
            wp.v[4 * i + 0] = make_float2(a.x, e.x);
            wp.v[4 * i + 1] = make_float2(a.y, e.y);
            wp.v[4 * i + 2] = make_float2(a.z, e.z);
            wp.v[4 * i + 3] = make_float2(a.w, e.w);
        }
    }

    // ---- helpers ----
    auto load_xrow = [&](int r) {
        const int slot = (r + 1) % 3;
        for (int i = tid; i < CPB * XW; i += NTH) {
            const int c  = i / XW;
            const int wq = i % XW;
            const int gw = wbase + wq - 1;
            float v = 0.f;
            if ((unsigned)r < (unsigned)HN && (unsigned)gw < (unsigned)WN)
                v = __ldg(x + (((size_t)b * CN + c0 + c) * HN + r) * WN + gw);
            sx[slot][wq][c] = v;
        }
    };

    constexpr float B0 = (float)(0.5 * 4.0 / 3.0 - 0.5);
    constexpr float B1 = (float)(1.5 * 4.0 / 3.0 - 0.5);
    constexpr float B2 = (float)(2.5 * 4.0 / 3.0 - 0.5);

    auto precompute = [&](int r) {
        for (int t = tid; t < WPB * 9; t += NTH) {
            const int tap = t / WPB;
            const int px  = t % WPB;
            const int kh = tap / 3, kw = tap % 3;
            const float* rp = rot + (((size_t)b * 18 + 2 * tap) * HN + r) * WN + wbase + px;
            const float ry = __ldg(rp);
            const float rx = __ldg(rp + HW);
            const float yb = (kh == 0) ? B0 : ((kh == 1) ? B1 : B2);
            const float xb = (kw == 0) ? B0 : ((kw == 1) ? B1 : B2);
            const float py = yb + ry, pxx = xb + rx;
            const float y0f = floorf(py), x0f = floorf(pxx);
            const float fy = py - y0f, fx = pxx - x0f;
            const bool vy0 = (y0f >=  0.f) && (y0f <= 3.f);
            const bool vy1 = (y0f >= -1.f) && (y0f <= 2.f);
            const bool vx0 = (x0f >=  0.f) && (x0f <= 3.f);
            const bool vx1 = (x0f >= -1.f) && (x0f <= 2.f);
            const float gy0 = 1.f - fy, gy1 = fy;
            const float gx0 = 1.f - fx, gx1 = fx;
            float4 cf;
            cf.x = (vy0 && vx0) ? gy0 * gx0 : 0.f;
            cf.y = (vy0 && vx1) ? gy0 * gx1 : 0.f;
            cf.z = (vy1 && vx0) ? gy1 * gx0 : 0.f;
            cf.w = (vy1 && vx1) ? gy1 * gx1 : 0.f;
            const int qy = (int)fminf(fmaxf(y0f, -1.f), 3.f) + 1;
            const int qx = (int)fminf(fmaxf(x0f, -1.f), 3.f) + 1;
            scf[px][tap] = cf;
            sqi[px][tap] = qy * 5 + qx;
        }
    };

    auto store_out = [&](int rr) {
        for (int i = tid; i < WPB * CPB; i += NTH) {
            const int c = i >> 5;
            const int w = i & 31;
            out[(((size_t)b * CN + c0 + c) * HN + rr) * WN + wbase + w] = so[w][c];
        }
    };

    // ---- prologue: rows r0-1, r0 into the ring ----
    load_xrow(r0 - 1);
    load_xrow(r0);

    for (int r = r0; r < r0 + RPB; r++) {
        // Phase A: fetch next x row, build coefs for row r, drain row r-1.
        load_xrow(r + 1);
        precompute(r);
        if (r > r0) store_out(r - 1);
        __syncthreads();

        // Phase B: compute row r. Each warp handles 4 contiguous pixels.
        const int s_m1 = r % 3;
        const int s_0  = (r + 1) % 3;
        const int s_p1 = (r + 2) % 3;

        #pragma unroll
        for (int pp = 0; pp < 4; pp++) {
            const int px = warp * 4 + pp;
            float2 acc = make_float2(0.f, 0.f);
            const float4* cfp = &scf[px][0];
            const int*    qp  = &sqi[px][0];

            #pragma unroll
            for (int kh = 0; kh < 3; kh++) {
                const float* xr = &sx[(kh == 0) ? s_m1 : ((kh == 1) ? s_0 : s_p1)][0][0];
                #pragma unroll 1
                for (int kw = 0; kw < 3; kw++) {
                    const int tp = kh * 3 + kw;
                    const float4 cf = cfp[tp];             // uniform broadcast
                    const int    qi = qp[tp];              // uniform broadcast
                    const float2 xv = *reinterpret_cast<const float2*>(
                        xr + (px + kw) * XC + 2 * lane);   // lane-contiguous
                    const float2 g = qblend(qi, wp, cf);
                    acc.x = fmaf(g.x, xv.x, acc.x);
                    acc.y = fmaf(g.y, xv.y, acc.y);
                }
            }
            *reinterpret_cast<float2*>(&so[px][2 * lane]) = acc;
        }
        __syncthreads();
    }
    store_out(r0 + RPB - 1);
}

extern "C" void kernel_launch(void* const* d_in, const int* in_sizes, int n_in,
                              void* d_out, int out_size)
{
    const float* x   = (const float*)d_in[0];
    const float* rot = (const float*)d_in[1];
    const float* wgt = (const float*)d_in[2];
    float* out = (float*)d_out;

    dim3 block(NTH, 1, 1);
    dim3 grid(3 * (HN / RPB), BN, CN / CPB);   // 12 x 8 x 4 = 384 blocks
    sdw_kernel<<<grid, block>>>(x, rot, wgt, out);
}

// round 5
// speedup vs baseline: 1.5367x; 1.5367x over previous
#include <cuda_runtime.h>
#include <cuda_fp16.h>

// SampleDepthwise deformable depthwise conv — fp16 quad-table version.
// B=8, C=256, H=W=96, K=3, S=4, PAD=1.
//
// lanes = channel pairs (2 ch/lane). Per (pixel, tap) the bilinear coefs and
// quad index are warp-uniform; the 4 corner weights for all 64 block channels
// come from a per-block smem table [q][pair] in fp16 (8B per channel), so one
// LDS.128 per lane = 4 conflict-free wavefronts per warp-tap. No switch, no
// scatter. x staged through a 3-row smem ring in [w][channel] layout.

#define BN 8
#define CN 256
#define HN 96
#define WN 96
#define HW (HN * WN)

constexpr int CPB  = 64;          // channels per block
constexpr int NPAIR = CPB / 2;    // 32 channel pairs (one per lane)
constexpr int WPB  = 32;          // pixel columns per block
constexpr int RPB  = 24;          // rows per block
constexpr int NTH  = 256;         // 8 warps, 4 px each
constexpr int XW   = WPB + 2;     // 34 staged x columns
constexpr int XC   = CPB + 2;     // 66: even (float2-aligned), degree-2 staging conflicts only
constexpr int NQ   = 25;          // quads: y0 in [-1,3] x x0 in [-1,3]

// dynamic smem layout (bytes)
constexpr int OFF_SQ   = 0;                          // uint4 [NQ][NPAIR]   12800
constexpr int OFF_SX   = OFF_SQ  + NQ * NPAIR * 16;  // float [3][XW][XC]   26928
constexpr int OFF_SCF  = OFF_SX  + 3 * XW * XC * 4;  // float4 [9][WPB]      4608
constexpr int OFF_SQO  = OFF_SCF + 9 * WPB * 16;     // int   [9][WPB]       1152
constexpr int OFF_SO   = OFF_SQO + 9 * WPB * 4;      // float [WPB][XC]      8448
constexpr int SMEM_TOTAL = OFF_SO + WPB * XC * 4;    // 53936

__global__ __launch_bounds__(NTH, 3)
void sdw_kernel(const float* __restrict__ x,
                const float* __restrict__ rot,
                const float* __restrict__ wgt,
                float* __restrict__ out)
{
    extern __shared__ __align__(16) char smem[];
    uint4*  sq  = reinterpret_cast<uint4*>(smem + OFF_SQ);
    float*  sx  = reinterpret_cast<float*>(smem + OFF_SX);
    float4* scf = reinterpret_cast<float4*>(smem + OFF_SCF);
    int*    sqo = reinterpret_cast<int*>(smem + OFF_SQO);
    float*  so  = reinterpret_cast<float*>(smem + OFF_SO);

    const int tid  = threadIdx.x;
    const int lane = tid & 31;
    const int warp = tid >> 5;

    const int b     = blockIdx.y;
    const int c0    = blockIdx.z * CPB;
    const int wbase = (blockIdx.x % 3) * WPB;
    const int r0    = (blockIdx.x / 3) * RPB;

    // ---- fp16 quad table: sq[q][pair] = {h2(w00a,w00b), h2(w01..), h2(w10..), h2(w11..)} ----
    for (int i = tid; i < NQ * NPAIR; i += NTH) {
        const int q  = i / NPAIR;
        const int p  = i % NPAIR;
        const int y0 = q / 5 - 1;
        const int x0 = q % 5 - 1;
        const float* wa = wgt + (c0 + 2 * p) * 16;
        const float* wb = wa + 16;
        auto corner = [&](const float* wc, int y, int xq) -> float {
            return (y >= 0 && y < 4 && xq >= 0 && xq < 4) ? __ldg(wc + y * 4 + xq) : 0.f;
        };
        const half2 e0 = __floats2half2_rn(corner(wa, y0,     x0    ), corner(wb, y0,     x0    ));
        const half2 e1 = __floats2half2_rn(corner(wa, y0,     x0 + 1), corner(wb, y0,     x0 + 1));
        const half2 e2 = __floats2half2_rn(corner(wa, y0 + 1, x0    ), corner(wb, y0 + 1, x0    ));
        const half2 e3 = __floats2half2_rn(corner(wa, y0 + 1, x0 + 1), corner(wb, y0 + 1, x0 + 1));
        uint4 u;
        u.x = *reinterpret_cast<const unsigned int*>(&e0);
        u.y = *reinterpret_cast<const unsigned int*>(&e1);
        u.z = *reinterpret_cast<const unsigned int*>(&e2);
        u.w = *reinterpret_cast<const unsigned int*>(&e3);
        sq[i] = u;
    }

    // ---- helpers ----
    auto load_xrow = [&](int r) {
        float* dst = sx + ((r + 1) % 3) * (XW * XC);
        for (int i = tid; i < CPB * XW; i += NTH) {
            const int c  = i / XW;
            const int wq = i % XW;
            const int gw = wbase + wq - 1;
            float v = 0.f;
            if ((unsigned)r < (unsigned)HN && (unsigned)gw < (unsigned)WN)
                v = __ldg(x + (((size_t)b * CN + c0 + c) * HN + r) * WN + gw);
            dst[wq * XC + c] = v;
        }
    };

    constexpr float B0 = (float)(0.5 * 4.0 / 3.0 - 0.5);
    constexpr float B1 = (float)(1.5 * 4.0 / 3.0 - 0.5);
    constexpr float B2 = (float)(2.5 * 4.0 / 3.0 - 0.5);

    auto precompute = [&](int r) {
        for (int t = tid; t < 9 * WPB; t += NTH) {
            const int tap = t / WPB;
            const int px  = t % WPB;
            const int kh = tap / 3, kw = tap % 3;
            const float* rp = rot + (((size_t)b * 18 + 2 * tap) * HN + r) * WN + wbase + px;
            const float ry = __ldg(rp);
            const float rx = __ldg(rp + HW);
            const float yb = (kh == 0) ? B0 : ((kh == 1) ? B1 : B2);
            const float xb = (kw == 0) ? B0 : ((kw == 1) ? B1 : B2);
            const float py = yb + ry, pxx = xb + rx;
            const float y0f = floorf(py), x0f = floorf(pxx);
            const float fy = py - y0f, fx = pxx - x0f;
            const bool vy0 = (y0f >=  0.f) && (y0f <= 3.f);
            const bool vy1 = (y0f >= -1.f) && (y0f <= 2.f);
            const bool vx0 = (x0f >=  0.f) && (x0f <= 3.f);
            const bool vx1 = (x0f >= -1.f) && (x0f <= 2.f);
            const float gy0 = 1.f - fy, gy1 = fy;
            const float gx0 = 1.f - fx, gx1 = fx;
            float4 cf;
            cf.x = (vy0 && vx0) ? gy0 * gx0 : 0.f;
            cf.y = (vy0 && vx1) ? gy0 * gx1 : 0.f;
            cf.z = (vy1 && vx0) ? gy1 * gx0 : 0.f;
            cf.w = (vy1 && vx1) ? gy1 * gx1 : 0.f;
            const int qy = (int)fminf(fmaxf(y0f, -1.f), 3.f) + 1;
            const int qx = (int)fminf(fmaxf(x0f, -1.f), 3.f) + 1;
            scf[t] = cf;
            sqo[t] = (qy * 5 + qx) * (NPAIR * 16);   // byte offset into sq
        }
    };

    auto store_out = [&](int rr) {
        for (int i = tid; i < WPB * CPB; i += NTH) {
            const int w = i & 31;
            const int c = i >> 5;
            out[(((size_t)b * CN + c0 + c) * HN + rr) * WN + wbase + w] = so[w * XC + c];
        }
    };

    // ---- prologue ----
    load_xrow(r0 - 1);
    load_xrow(r0);

    for (int r = r0; r < r0 + RPB; r++) {
        load_xrow(r + 1);
        precompute(r);
        if (r > r0) store_out(r - 1);
        __syncthreads();

        const float* row_m1 = sx + ( r      % 3) * (XW * XC);
        const float* row_0  = sx + ((r + 1) % 3) * (XW * XC);
        const float* row_p1 = sx + ((r + 2) % 3) * (XW * XC);
        const char* sqc = reinterpret_cast<const char*>(sq) + lane * 16;

        #pragma unroll 1
        for (int pp = 0; pp < 4; pp++) {
            const int px = warp * 4 + pp;
            float a0 = 0.f, a1 = 0.f;
            #pragma unroll
            for (int kh = 0; kh < 3; kh++) {
                const float* xr = (kh == 0) ? row_m1 : ((kh == 1) ? row_0 : row_p1);
                #pragma unroll
                for (int kw = 0; kw < 3; kw++) {
                    const int tp = kh * 3 + kw;
                    const float4 cf = scf[tp * WPB + px];     // uniform broadcast
                    const int    qo = sqo[tp * WPB + px];     // uniform broadcast
                    const uint4  qv = *reinterpret_cast<const uint4*>(sqc + qo);
                    const float2 f00 = __half22float2(*reinterpret_cast<const half2*>(&qv.x));
                    const float2 f01 = __half22float2(*reinterpret_cast<const half2*>(&qv.y));
                    const float2 f10 = __half22float2(*reinterpret_cast<const half2*>(&qv.z));
                    const float2 f11 = __half22float2(*reinterpret_cast<const half2*>(&qv.w));
                    const float2 xv  = *reinterpret_cast<const float2*>(xr + (px + kw) * XC + 2 * lane);
                    const float g0 = fmaf(cf.x, f00.x, fmaf(cf.y, f01.x, fmaf(cf.z, f10.x, cf.w * f11.x)));
                    const float g1 = fmaf(cf.x, f00.y, fmaf(cf.y, f01.y, fmaf(cf.z, f10.y, cf.w * f11.y)));
                    a0 = fmaf(g0, xv.x, a0);
                    a1 = fmaf(g1, xv.y, a1);
                }
            }
            *reinterpret_cast<float2*>(so + px * XC + 2 * lane) = make_float2(a0, a1);
        }
        __syncthreads();
    }
    store_out(r0 + RPB - 1);
}

extern "C" void kernel_launch(void* const* d_in, const int* in_sizes, int n_in,
                              void* d_out, int out_size)
{
    const float* x   = (const float*)d_in[0];
    const float* rot = (const float*)d_in[1];
    const float* wgt = (const float*)d_in[2];
    float* out = (float*)d_out;

    cudaFuncSetAttribute(sdw_kernel, cudaFuncAttributeMaxDynamicSharedMemorySize, SMEM_TOTAL);

    dim3 block(NTH, 1, 1);
    dim3 grid(3 * (HN / RPB), BN, CN / CPB);   // 12 x 8 x 4 = 384 blocks
    sdw_kernel<<<grid, block, SMEM_TOTAL>>>(x, rot, wgt, out);
}

// round 6
// speedup vs baseline: 1.8118x; 1.1790x over previous
#include <cuda_runtime.h>
#include <cuda_fp16.h>

// SampleDepthwise deformable depthwise conv — fp16 quad table + HFMA2 blend.
// B=8, C=256, H=W=96, K=3, S=4, PAD=1.
//
// lanes = channel pairs (2 ch/lane). Per (pixel, tap): coefs pre-packed as
// duplicated half2 (one LDS.128), quad weights one LDS.128, blend = 1 HMUL2 +
// 3 HFMA2, only the blended g converted to f32 (2 cvt), acc = 2 FFMA.
// x values reused across (pp, kw): 6 float2 loads per kh cover 12 taps.

#define BN 8
#define CN 256
#define HN 96
#define WN 96
#define HW (HN * WN)

constexpr int CPB  = 64;          // channels per block
constexpr int NPAIR = CPB / 2;    // 32 channel pairs (one per lane)
constexpr int WPB  = 32;          // pixel columns per block
constexpr int RPB  = 24;          // rows per block
constexpr int NTH  = 256;         // 8 warps, 4 px each
constexpr int XW   = WPB + 2;     // 34 staged x columns
constexpr int XC   = CPB + 2;     // 66 floats (float2-aligned)
constexpr int NQ   = 25;          // quads: y0 in [-1,3] x x0 in [-1,3]

// dynamic smem layout (bytes)
constexpr int OFF_SQ   = 0;                          // uint4 [NQ][NPAIR]   12800
constexpr int OFF_SX   = OFF_SQ  + NQ * NPAIR * 16;  // float [3][XW][XC]   26928
constexpr int OFF_SCF  = OFF_SX  + 3 * XW * XC * 4;  // uint4 [9][WPB]       4608
constexpr int OFF_SQO  = OFF_SCF + 9 * WPB * 16;     // int   [9][WPB]       1152
constexpr int OFF_SO   = OFF_SQO + 9 * WPB * 4;      // float [WPB][XC]      8448
constexpr int SMEM_TOTAL = OFF_SO + WPB * XC * 4;    // 53936

static __device__ __forceinline__ half2 u2h(unsigned int u) {
    half2 h;
    *reinterpret_cast<unsigned int*>(&h) = u;
    return h;
}
static __device__ __forceinline__ unsigned int h2u(half2 h) {
    return *reinterpret_cast<unsigned int*>(&h);
}

__global__ __launch_bounds__(NTH, 3)
void sdw_kernel(const float* __restrict__ x,
                const float* __restrict__ rot,
                const float* __restrict__ wgt,
                float* __restrict__ out)
{
    extern __shared__ __align__(16) char smem[];
    uint4*  sq  = reinterpret_cast<uint4*>(smem + OFF_SQ);
    float*  sx  = reinterpret_cast<float*>(smem + OFF_SX);
    uint4*  scf = reinterpret_cast<uint4*>(smem + OFF_SCF);
    int*    sqo = reinterpret_cast<int*>(smem + OFF_SQO);
    float*  so  = reinterpret_cast<float*>(smem + OFF_SO);

    const int tid  = threadIdx.x;
    const int lane = tid & 31;
    const int warp = tid >> 5;

    const int b     = blockIdx.y;
    const int c0    = blockIdx.z * CPB;
    const int wbase = (blockIdx.x % 3) * WPB;
    const int r0    = (blockIdx.x / 3) * RPB;

    // ---- fp16 quad table: sq[q][pair] = {h2(w00a,w00b), ..., h2(w11a,w11b)} ----
    for (int i = tid; i < NQ * NPAIR; i += NTH) {
        const int q  = i / NPAIR;
        const int p  = i % NPAIR;
        const int y0 = q / 5 - 1;
        const int x0 = q % 5 - 1;
        const float* wa = wgt + (c0 + 2 * p) * 16;
        const float* wb = wa + 16;
        auto corner = [&](const float* wc, int y, int xq) -> float {
            return (y >= 0 && y < 4 && xq >= 0 && xq < 4) ? __ldg(wc + y * 4 + xq) : 0.f;
        };
        uint4 u;
        u.x = h2u(__floats2half2_rn(corner(wa, y0,     x0    ), corner(wb, y0,     x0    )));
        u.y = h2u(__floats2half2_rn(corner(wa, y0,     x0 + 1), corner(wb, y0,     x0 + 1)));
        u.z = h2u(__floats2half2_rn(corner(wa, y0 + 1, x0    ), corner(wb, y0 + 1, x0    )));
        u.w = h2u(__floats2half2_rn(corner(wa, y0 + 1, x0 + 1), corner(wb, y0 + 1, x0 + 1)));
        sq[i] = u;
    }

    // ---- helpers ----
    auto load_xrow = [&](int r) {
        float* dst = sx + ((r + 1) % 3) * (XW * XC);
        const bool rvalid = (unsigned)r < (unsigned)HN;
        const int  rr = rvalid ? r : 0;
        const float* src = x + (((size_t)b * CN + c0) * HN + rr) * WN + wbase;
        // bulk: dst cols 1..32 <-> gw = wbase+0..31 (always in range)
        const int w_ = tid & 31;
        const int cb = tid >> 5;
        #pragma unroll
        for (int k = 0; k < 8; k++) {
            const int c = cb + k * 8;
            dst[(1 + w_) * XC + c] = rvalid ? __ldg(src + (size_t)c * HW + w_) : 0.f;
        }
        // halo: dst cols 0 and 33
        if (tid < 128) {
            const int c    = tid >> 1;
            const int side = tid & 1;
            const int wq   = side ? 33 : 0;
            const int gw   = wbase + wq - 1;
            float v = 0.f;
            if (rvalid && (unsigned)gw < (unsigned)WN)
                v = __ldg(x + (((size_t)b * CN + c0 + c) * HN + rr) * WN + gw);
            dst[wq * XC + c] = v;
        }
    };

    constexpr float B0 = (float)(0.5 * 4.0 / 3.0 - 0.5);
    constexpr float B1 = (float)(1.5 * 4.0 / 3.0 - 0.5);
    constexpr float B2 = (float)(2.5 * 4.0 / 3.0 - 0.5);

    auto precompute = [&](int r) {
        for (int t = tid; t < 9 * WPB; t += NTH) {
            const int tap = t >> 5;
            const int px  = t & 31;
            const int kh = tap / 3, kw = tap % 3;
            const float* rp = rot + (((size_t)b * 18 + 2 * tap) * HN + r) * WN + wbase + px;
            const float ry = __ldg(rp);
            const float rx = __ldg(rp + HW);
            const float yb = (kh == 0) ? B0 : ((kh == 1) ? B1 : B2);
            const float xb = (kw == 0) ? B0 : ((kw == 1) ? B1 : B2);
            const float py = yb + ry, pxx = xb + rx;
            const float y0f = floorf(py), x0f = floorf(pxx);
            const float fy = py - y0f, fx = pxx - x0f;
            const bool vy0 = (y0f >=  0.f) && (y0f <= 3.f);
            const bool vy1 = (y0f >= -1.f) && (y0f <= 2.f);
            const bool vx0 = (x0f >=  0.f) && (x0f <= 3.f);
            const bool vx1 = (x0f >= -1.f) && (x0f <= 2.f);
            const float gy0 = 1.f - fy, gy1 = fy;
            const float gx0 = 1.f - fx, gx1 = fx;
            uint4 pc;
            pc.x = h2u(__float2half2_rn((vy0 && vx0) ? gy0 * gx0 : 0.f));
            pc.y = h2u(__float2half2_rn((vy0 && vx1) ? gy0 * gx1 : 0.f));
            pc.z = h2u(__float2half2_rn((vy1 && vx0) ? gy1 * gx0 : 0.f));
            pc.w = h2u(__float2half2_rn((vy1 && vx1) ? gy1 * gx1 : 0.f));
            const int qy = (int)fminf(fmaxf(y0f, -1.f), 3.f) + 1;
            const int qx = (int)fminf(fmaxf(x0f, -1.f), 3.f) + 1;
            scf[t] = pc;
            sqo[t] = (qy * 5 + qx) * (NPAIR * 16);   // byte offset into sq
        }
    };

    auto store_out = [&](int rr) {
        for (int i = tid; i < WPB * CPB; i += NTH) {
            const int w = i & 31;
            const int c = i >> 5;
            out[(((size_t)b * CN + c0 + c) * HN + rr) * WN + wbase + w] = so[w * XC + c];
        }
    };

    // ---- prologue ----
    load_xrow(r0 - 1);
    load_xrow(r0);

    const char* sqc = reinterpret_cast<const char*>(sq) + lane * 16;
    const int p0 = warp * 4;

    for (int r = r0; r < r0 + RPB; r++) {
        load_xrow(r + 1);
        precompute(r);
        if (r > r0) store_out(r - 1);
        __syncthreads();

        const float* row_m1 = sx + ( r      % 3) * (XW * XC);
        const float* row_0  = sx + ((r + 1) % 3) * (XW * XC);
        const float* row_p1 = sx + ((r + 2) % 3) * (XW * XC);

        float2 acc[4];
        #pragma unroll
        for (int pp = 0; pp < 4; pp++) acc[pp] = make_float2(0.f, 0.f);

        #pragma unroll
        for (int kh = 0; kh < 3; kh++) {
            const float* xr = (kh == 0) ? row_m1 : ((kh == 1) ? row_0 : row_p1);
            float2 xv[6];
            #pragma unroll
            for (int j = 0; j < 6; j++)
                xv[j] = *reinterpret_cast<const float2*>(xr + (p0 + j) * XC + 2 * lane);

            #pragma unroll
            for (int kw = 0; kw < 3; kw++) {
                const int tp = kh * 3 + kw;
                const uint4* cfp = scf + tp * WPB + p0;
                const int*   qp  = sqo + tp * WPB + p0;
                #pragma unroll
                for (int pp = 0; pp < 4; pp++) {
                    const uint4 cfu = cfp[pp];                        // uniform broadcast
                    const int   qo  = qp[pp];                         // uniform broadcast
                    const uint4 qv  = *reinterpret_cast<const uint4*>(sqc + qo);
                    half2 g2 = __hmul2(u2h(cfu.x), u2h(qv.x));
                    g2 = __hfma2(u2h(cfu.y), u2h(qv.y), g2);
                    g2 = __hfma2(u2h(cfu.z), u2h(qv.z), g2);
                    g2 = __hfma2(u2h(cfu.w), u2h(qv.w), g2);
                    const float2 g  = __half22float2(g2);
                    const float2 xx = xv[pp + kw];
                    acc[pp].x = fmaf(g.x, xx.x, acc[pp].x);
                    acc[pp].y = fmaf(g.y, xx.y, acc[pp].y);
                }
            }
        }

        #pragma unroll
        for (int pp = 0; pp < 4; pp++)
            *reinterpret_cast<float2*>(so + (p0 + pp) * XC + 2 * lane) = acc[pp];
        __syncthreads();
    }
    store_out(r0 + RPB - 1);
}

extern "C" void kernel_launch(void* const* d_in, const int* in_sizes, int n_in,
                              void* d_out, int out_size)
{
    const float* x   = (const float*)d_in[0];
    const float* rot = (const float*)d_in[1];
    const float* wgt = (const float*)d_in[2];
    float* out = (float*)d_out;

    cudaFuncSetAttribute(sdw_kernel, cudaFuncAttributeMaxDynamicSharedMemorySize, SMEM_TOTAL);

    dim3 block(NTH, 1, 1);
    dim3 grid(3 * (HN / RPB), BN, CN / CPB);   // 12 x 8 x 4 = 384 blocks
    sdw_kernel<<<grid, block, SMEM_TOTAL>>>(x, rot, wgt, out);
}

// round 7
// speedup vs baseline: 1.8829x; 1.0393x over previous
#include <cuda_runtime.h>
#include <cuda_fp16.h>

// SampleDepthwise deformable depthwise conv — fp16 quad table + HFMA2 blend,
// fused cf/qo broadcast, 4 blocks/SM.
// B=8, C=256, H=W=96, K=3, S=4, PAD=1.
//
// lanes = channel pairs (2 ch/lane). Per (pixel, tap): ONE uniform uint4 LDS
// carries {half2(c00,c01), half2(c10,c11), quad-byte-offset, pad}; duplicated
// half2 coefs rebuilt via PRMT; quad weights one lane-contiguous LDS.128;
// blend = 1 HMUL2 + 3 HFMA2; g converted once; acc = 2 FFMA.

#define BN 8
#define CN 256
#define HN 96
#define WN 96
#define HW (HN * WN)

constexpr int CPB  = 64;          // channels per block
constexpr int NPAIR = CPB / 2;    // 32 channel pairs (one per lane)
constexpr int WPB  = 32;          // pixel columns per block
constexpr int RPB  = 24;          // rows per block
constexpr int NTH  = 256;         // 8 warps, 4 px each
constexpr int XW   = WPB + 2;     // 34 staged x columns
constexpr int XC   = CPB + 2;     // 66 floats (float2-aligned, degree-2 staging conflicts)
constexpr int NQ   = 25;          // quads: y0 in [-1,3] x x0 in [-1,3]

// dynamic smem layout (bytes)
constexpr int OFF_SQ   = 0;                          // uint4 [NQ][NPAIR]   12800
constexpr int OFF_SX   = OFF_SQ  + NQ * NPAIR * 16;  // float [3][XW][XC]   26928
constexpr int OFF_SCF  = OFF_SX  + 3 * XW * XC * 4;  // uint4 [9][WPB]       4608
constexpr int OFF_SO   = OFF_SCF + 9 * WPB * 16;     // float [WPB][XC]      8448
constexpr int SMEM_TOTAL = OFF_SO + WPB * XC * 4;    // 52784

static __device__ __forceinline__ half2 u2h(unsigned int u) {
    half2 h;
    *reinterpret_cast<unsigned int*>(&h) = u;
    return h;
}
static __device__ __forceinline__ unsigned int h2u(half2 h) {
    return *reinterpret_cast<unsigned int*>(&h);
}

__global__ __launch_bounds__(NTH, 4)
void sdw_kernel(const float* __restrict__ x,
                const float* __restrict__ rot,
                const float* __restrict__ wgt,
                float* __restrict__ out)
{
    extern __shared__ __align__(16) char smem[];
    uint4*  sq  = reinterpret_cast<uint4*>(smem + OFF_SQ);
    float*  sx  = reinterpret_cast<float*>(smem + OFF_SX);
    uint4*  scf = reinterpret_cast<uint4*>(smem + OFF_SCF);
    float*  so  = reinterpret_cast<float*>(smem + OFF_SO);

    const int tid  = threadIdx.x;
    const int lane = tid & 31;
    const int warp = tid >> 5;

    const int b     = blockIdx.y;
    const int c0    = blockIdx.z * CPB;
    const int wbase = (blockIdx.x % 3) * WPB;
    const int r0    = (blockIdx.x / 3) * RPB;

    // ---- fp16 quad table: sq[q][pair] = {h2(w00a,w00b), ..., h2(w11a,w11b)} ----
    for (int i = tid; i < NQ * NPAIR; i += NTH) {
        const int q  = i / NPAIR;
        const int p  = i % NPAIR;
        const int y0 = q / 5 - 1;
        const int x0 = q % 5 - 1;
        const float* wa = wgt + (c0 + 2 * p) * 16;
        const float* wb = wa + 16;
        auto corner = [&](const float* wc, int y, int xq) -> float {
            return (y >= 0 && y < 4 && xq >= 0 && xq < 4) ? __ldg(wc + y * 4 + xq) : 0.f;
        };
        uint4 u;
        u.x = h2u(__floats2half2_rn(corner(wa, y0,     x0    ), corner(wb, y0,     x0    )));
        u.y = h2u(__floats2half2_rn(corner(wa, y0,     x0 + 1), corner(wb, y0,     x0 + 1)));
        u.z = h2u(__floats2half2_rn(corner(wa, y0 + 1, x0    ), corner(wb, y0 + 1, x0    )));
        u.w = h2u(__floats2half2_rn(corner(wa, y0 + 1, x0 + 1), corner(wb, y0 + 1, x0 + 1)));
        sq[i] = u;
    }

    // ---- helpers ----
    auto load_xrow = [&](int r) {
        float* dst = sx + ((r + 1) % 3) * (XW * XC);
        const bool rvalid = (unsigned)r < (unsigned)HN;
        const int  rr = rvalid ? r : 0;
        const float* src = x + (((size_t)b * CN + c0) * HN + rr) * WN + wbase;
        const int w_ = tid & 31;
        const int cb = tid >> 5;
        #pragma unroll
        for (int k = 0; k < 8; k++) {
            const int c = cb + k * 8;
            dst[(1 + w_) * XC + c] = rvalid ? __ldg(src + (size_t)c * HW + w_) : 0.f;
        }
        if (tid < 128) {
            const int c    = tid >> 1;
            const int side = tid & 1;
            const int wq   = side ? 33 : 0;
            const int gw   = wbase + wq - 1;
            float v = 0.f;
            if (rvalid && (unsigned)gw < (unsigned)WN)
                v = __ldg(x + (((size_t)b * CN + c0 + c) * HN + rr) * WN + gw);
            dst[wq * XC + c] = v;
        }
    };

    constexpr float B0 = (float)(0.5 * 4.0 / 3.0 - 0.5);
    constexpr float B1 = (float)(1.5 * 4.0 / 3.0 - 0.5);
    constexpr float B2 = (float)(2.5 * 4.0 / 3.0 - 0.5);

    auto precompute = [&](int r) {
        for (int t = tid; t < 9 * WPB; t += NTH) {
            const int tap = t >> 5;
            const int px  = t & 31;
            const int kh = tap / 3, kw = tap % 3;
            const float* rp = rot + (((size_t)b * 18 + 2 * tap) * HN + r) * WN + wbase + px;
            const float ry = __ldg(rp);
            const float rx = __ldg(rp + HW);
            const float yb = (kh == 0) ? B0 : ((kh == 1) ? B1 : B2);
            const float xb = (kw == 0) ? B0 : ((kw == 1) ? B1 : B2);
            const float py = yb + ry, pxx = xb + rx;
            const float y0f = floorf(py), x0f = floorf(pxx);
            const float fy = py - y0f, fx = pxx - x0f;
            const bool vy0 = (y0f >=  0.f) && (y0f <= 3.f);
            const bool vy1 = (y0f >= -1.f) && (y0f <= 2.f);
            const bool vx0 = (x0f >=  0.f) && (x0f <= 3.f);
            const bool vx1 = (x0f >= -1.f) && (x0f <= 2.f);
            const float gy0 = 1.f - fy, gy1 = fy;
            const float gx0 = 1.f - fx, gx1 = fx;
            const float c00 = (vy0 && vx0) ? gy0 * gx0 : 0.f;
            const float c01 = (vy0 && vx1) ? gy0 * gx1 : 0.f;
            const float c10 = (vy1 && vx0) ? gy1 * gx0 : 0.f;
            const float c11 = (vy1 && vx1) ? gy1 * gx1 : 0.f;
            const int qy = (int)fminf(fmaxf(y0f, -1.f), 3.f) + 1;
            const int qx = (int)fminf(fmaxf(x0f, -1.f), 3.f) + 1;
            uint4 pc;
            pc.x = h2u(__floats2half2_rn(c00, c01));
            pc.y = h2u(__floats2half2_rn(c10, c11));
            pc.z = (unsigned)((qy * 5 + qx) * (NPAIR * 16));  // byte offset into sq
            pc.w = 0u;
            scf[t] = pc;
        }
    };

    auto store_out = [&](int rr) {
        for (int i = tid; i < WPB * CPB; i += NTH) {
            const int w = i & 31;
            const int c = i >> 5;
            out[(((size_t)b * CN + c0 + c) * HN + rr) * WN + wbase + w] = so[w * XC + c];
        }
    };

    // ---- prologue ----
    load_xrow(r0 - 1);
    load_xrow(r0);

    const char* sqc = reinterpret_cast<const char*>(sq) + lane * 16;
    const int p0 = warp * 4;

    for (int r = r0; r < r0 + RPB; r++) {
        load_xrow(r + 1);
        precompute(r);
        if (r > r0) store_out(r - 1);
        __syncthreads();

        const float* row_m1 = sx + ( r      % 3) * (XW * XC);
        const float* row_0  = sx + ((r + 1) % 3) * (XW * XC);
        const float* row_p1 = sx + ((r + 2) % 3) * (XW * XC);

        float2 acc[4];
        #pragma unroll
        for (int pp = 0; pp < 4; pp++) acc[pp] = make_float2(0.f, 0.f);

        #pragma unroll
        for (int kh = 0; kh < 3; kh++) {
            const float* xr = (kh == 0) ? row_m1 : ((kh == 1) ? row_0 : row_p1);
            float2 xv[6];
            #pragma unroll
            for (int j = 0; j < 6; j++)
                xv[j] = *reinterpret_cast<const float2*>(xr + (p0 + j) * XC + 2 * lane);

            #pragma unroll
            for (int kw = 0; kw < 3; kw++) {
                const uint4* cfp = scf + (kh * 3 + kw) * WPB + p0;
                #pragma unroll
                for (int pp = 0; pp < 4; pp++) {
                    const uint4 cfu = cfp[pp];                        // uniform broadcast
                    const uint4 qv  = *reinterpret_cast<const uint4*>(sqc + cfu.z);
                    const half2 cl  = u2h(cfu.x);                     // (c00, c01)
                    const half2 chh = u2h(cfu.y);                     // (c10, c11)
                    half2 g2 = __hmul2(__low2half2(cl),  u2h(qv.x));
                    g2 = __hfma2(__high2half2(cl),  u2h(qv.y), g2);
                    g2 = __hfma2(__low2half2(chh),  u2h(qv.z), g2);
                    g2 = __hfma2(__high2half2(chh), u2h(qv.w), g2);
                    const float2 g  = __half22float2(g2);
                    const float2 xx = xv[pp + kw];
                    acc[pp].x = fmaf(g.x, xx.x, acc[pp].x);
                    acc[pp].y = fmaf(g.y, xx.y, acc[pp].y);
                }
            }
        }

        #pragma unroll
        for (int pp = 0; pp < 4; pp++)
            *reinterpret_cast<float2*>(so + (p0 + pp) * XC + 2 * lane) = acc[pp];
        __syncthreads();
    }
    store_out(r0 + RPB - 1);
}

extern "C" void kernel_launch(void* const* d_in, const int* in_sizes, int n_in,
                              void* d_out, int out_size)
{
    const float* x   = (const float*)d_in[0];
    const float* rot = (const float*)d_in[1];
    const float* wgt = (const float*)d_in[2];
    float* out = (float*)d_out;

    cudaFuncSetAttribute(sdw_kernel, cudaFuncAttributeMaxDynamicSharedMemorySize, SMEM_TOTAL);

    dim3 block(NTH, 1, 1);
    dim3 grid(3 * (HN / RPB), BN, CN / CPB);   // 12 x 8 x 4 = 384 blocks
    sdw_kernel<<<grid, block, SMEM_TOTAL>>>(x, rot, wgt, out);
}

// round 8
// speedup vs baseline: 2.0940x; 1.1121x over previous
#include <cuda_runtime.h>
#include <cuda_fp16.h>

// SampleDepthwise deformable depthwise conv — fp16 quad table + HFMA2 blend,
// fused cf/qo broadcast, RPB=16 -> 576-block single-wave grid (4 blocks/SM).
// B=8, C=256, H=W=96, K=3, S=4, PAD=1.
//
// lanes = channel pairs (2 ch/lane). Per (pixel, tap): ONE uniform uint4 LDS
// carries {half2(c00,c01), half2(c10,c11), quad-byte-offset, pad}; duplicated
// half2 coefs rebuilt via PRMT; quad weights one lane-contiguous LDS.128;
// blend = 1 HMUL2 + 3 HFMA2; g converted once; acc = 2 FFMA.

#define BN 8
#define CN 256
#define HN 96
#define WN 96
#define HW (HN * WN)

constexpr int CPB  = 64;          // channels per block
constexpr int NPAIR = CPB / 2;    // 32 channel pairs (one per lane)
constexpr int WPB  = 32;          // pixel columns per block
constexpr int RPB  = 16;          // rows per block -> 576 blocks, single wave
constexpr int NTH  = 256;         // 8 warps, 4 px each
constexpr int XW   = WPB + 2;     // 34 staged x columns
constexpr int XC   = CPB + 2;     // 66 floats (float2-aligned)
constexpr int NQ   = 25;          // quads: y0 in [-1,3] x x0 in [-1,3]

// dynamic smem layout (bytes)
constexpr int OFF_SQ   = 0;                          // uint4 [NQ][NPAIR]   12800
constexpr int OFF_SX   = OFF_SQ  + NQ * NPAIR * 16;  // float [3][XW][XC]   26928
constexpr int OFF_SCF  = OFF_SX  + 3 * XW * XC * 4;  // uint4 [9][WPB]       4608
constexpr int OFF_SO   = OFF_SCF + 9 * WPB * 16;     // float [WPB][XC]      8448
constexpr int SMEM_TOTAL = OFF_SO + WPB * XC * 4;    // 52784

static __device__ __forceinline__ half2 u2h(unsigned int u) {
    half2 h;
    *reinterpret_cast<unsigned int*>(&h) = u;
    return h;
}
static __device__ __forceinline__ unsigned int h2u(half2 h) {
    return *reinterpret_cast<unsigned int*>(&h);
}

__global__ __launch_bounds__(NTH, 4)
void sdw_kernel(const float* __restrict__ x,
                const float* __restrict__ rot,
                const float* __restrict__ wgt,
                float* __restrict__ out)
{
    extern __shared__ __align__(16) char smem[];
    uint4*  sq  = reinterpret_cast<uint4*>(smem + OFF_SQ);
    float*  sx  = reinterpret_cast<float*>(smem + OFF_SX);
    uint4*  scf = reinterpret_cast<uint4*>(smem + OFF_SCF);
    float*  so  = reinterpret_cast<float*>(smem + OFF_SO);

    const int tid  = threadIdx.x;
    const int lane = tid & 31;
    const int warp = tid >> 5;

    const int b     = blockIdx.y;
    const int c0    = blockIdx.z * CPB;
    const int wbase = (blockIdx.x % 3) * WPB;
    const int r0    = (blockIdx.x / 3) * RPB;

    // ---- fp16 quad table: sq[q][pair] = {h2(w00a,w00b), ..., h2(w11a,w11b)} ----
    for (int i = tid; i < NQ * NPAIR; i += NTH) {
        const int q  = i / NPAIR;
        const int p  = i % NPAIR;
        const int y0 = q / 5 - 1;
        const int x0 = q % 5 - 1;
        const float* wa = wgt + (c0 + 2 * p) * 16;
        const float* wb = wa + 16;
        auto corner = [&](const float* wc, int y, int xq) -> float {
            return (y >= 0 && y < 4 && xq >= 0 && xq < 4) ? __ldg(wc + y * 4 + xq) : 0.f;
        };
        uint4 u;
        u.x = h2u(__floats2half2_rn(corner(wa, y0,     x0    ), corner(wb, y0,     x0    )));
        u.y = h2u(__floats2half2_rn(corner(wa, y0,     x0 + 1), corner(wb, y0,     x0 + 1)));
        u.z = h2u(__floats2half2_rn(corner(wa, y0 + 1, x0    ), corner(wb, y0 + 1, x0    )));
        u.w = h2u(__floats2half2_rn(corner(wa, y0 + 1, x0 + 1), corner(wb, y0 + 1, x0 + 1)));
        sq[i] = u;
    }

    // ---- helpers ----
    auto load_xrow = [&](int r) {
        float* dst = sx + ((r + 1) % 3) * (XW * XC);
        const bool rvalid = (unsigned)r < (unsigned)HN;
        const int  rr = rvalid ? r : 0;
        const float* src = x + (((size_t)b * CN + c0) * HN + rr) * WN + wbase;
        const int w_ = tid & 31;
        const int cb = tid >> 5;
        #pragma unroll
        for (int k = 0; k < 8; k++) {
            const int c = cb + k * 8;
            dst[(1 + w_) * XC + c] = rvalid ? __ldg(src + (size_t)c * HW + w_) : 0.f;
        }
        if (tid < 128) {
            const int c    = tid >> 1;
            const int side = tid & 1;
            const int wq   = side ? 33 : 0;
            const int gw   = wbase + wq - 1;
            float v = 0.f;
            if (rvalid && (unsigned)gw < (unsigned)WN)
                v = __ldg(x + (((size_t)b * CN + c0 + c) * HN + rr) * WN + gw);
            dst[wq * XC + c] = v;
        }
    };

    constexpr float B0 = (float)(0.5 * 4.0 / 3.0 - 0.5);
    constexpr float B1 = (float)(1.5 * 4.0 / 3.0 - 0.5);
    constexpr float B2 = (float)(2.5 * 4.0 / 3.0 - 0.5);

    auto precompute = [&](int r) {
        for (int t = tid; t < 9 * WPB; t += NTH) {
            const int tap = t >> 5;
            const int px  = t & 31;
            const int kh = tap / 3, kw = tap % 3;
            const float* rp = rot + (((size_t)b * 18 + 2 * tap) * HN + r) * WN + wbase + px;
            const float ry = __ldg(rp);
            const float rx = __ldg(rp + HW);
            const float yb = (kh == 0) ? B0 : ((kh == 1) ? B1 : B2);
            const float xb = (kw == 0) ? B0 : ((kw == 1) ? B1 : B2);
            const float py = yb + ry, pxx = xb + rx;
            const float y0f = floorf(py), x0f = floorf(pxx);
            const float fy = py - y0f, fx = pxx - x0f;
            const bool vy0 = (y0f >=  0.f) && (y0f <= 3.f);
            const bool vy1 = (y0f >= -1.f) && (y0f <= 2.f);
            const bool vx0 = (x0f >=  0.f) && (x0f <= 3.f);
            const bool vx1 = (x0f >= -1.f) && (x0f <= 2.f);
            const float gy0 = 1.f - fy, gy1 = fy;
            const float gx0 = 1.f - fx, gx1 = fx;
            const float c00 = (vy0 && vx0) ? gy0 * gx0 : 0.f;
            const float c01 = (vy0 && vx1) ? gy0 * gx1 : 0.f;
            const float c10 = (vy1 && vx0) ? gy1 * gx0 : 0.f;
            const float c11 = (vy1 && vx1) ? gy1 * gx1 : 0.f;
            const int qy = (int)fminf(fmaxf(y0f, -1.f), 3.f) + 1;
            const int qx = (int)fminf(fmaxf(x0f, -1.f), 3.f) + 1;
            uint4 pc;
            pc.x = h2u(__floats2half2_rn(c00, c01));
            pc.y = h2u(__floats2half2_rn(c10, c11));
            pc.z = (unsigned)((qy * 5 + qx) * (NPAIR * 16));  // byte offset into sq
            pc.w = 0u;
            scf[t] = pc;
        }
    };

    auto store_out = [&](int rr) {
        for (int i = tid; i < WPB * CPB; i += NTH) {
            const int w = i & 31;
            const int c = i >> 5;
            out[(((size_t)b * CN + c0 + c) * HN + rr) * WN + wbase + w] = so[w * XC + c];
        }
    };

    // ---- prologue ----
    load_xrow(r0 - 1);
    load_xrow(r0);

    const char* sqc = reinterpret_cast<const char*>(sq) + lane * 16;
    const int p0 = warp * 4;

    for (int r = r0; r < r0 + RPB; r++) {
        load_xrow(r + 1);
        precompute(r);
        if (r > r0) store_out(r - 1);
        __syncthreads();

        const float* row_m1 = sx + ( r      % 3) * (XW * XC);
        const float* row_0  = sx + ((r + 1) % 3) * (XW * XC);
        const float* row_p1 = sx + ((r + 2) % 3) * (XW * XC);

        float2 acc[4];
        #pragma unroll
        for (int pp = 0; pp < 4; pp++) acc[pp] = make_float2(0.f, 0.f);

        #pragma unroll
        for (int kh = 0; kh < 3; kh++) {
            const float* xr = (kh == 0) ? row_m1 : ((kh == 1) ? row_0 : row_p1);
            float2 xv[6];
            #pragma unroll
            for (int j = 0; j < 6; j++)
                xv[j] = *reinterpret_cast<const float2*>(xr + (p0 + j) * XC + 2 * lane);

            #pragma unroll
            for (int kw = 0; kw < 3; kw++) {
                const uint4* cfp = scf + (kh * 3 + kw) * WPB + p0;
                #pragma unroll
                for (int pp = 0; pp < 4; pp++) {
                    const uint4 cfu = cfp[pp];                        // uniform broadcast
                    const uint4 qv  = *reinterpret_cast<const uint4*>(sqc + cfu.z);
                    const half2 cl  = u2h(cfu.x);                     // (c00, c01)
                    const half2 chh = u2h(cfu.y);                     // (c10, c11)
                    half2 g2 = __hmul2(__low2half2(cl),  u2h(qv.x));
                    g2 = __hfma2(__high2half2(cl),  u2h(qv.y), g2);
                    g2 = __hfma2(__low2half2(chh),  u2h(qv.z), g2);
                    g2 = __hfma2(__high2half2(chh), u2h(qv.w), g2);
                    const float2 g  = __half22float2(g2);
                    const float2 xx = xv[pp + kw];
                    acc[pp].x = fmaf(g.x, xx.x, acc[pp].x);
                    acc[pp].y = fmaf(g.y, xx.y, acc[pp].y);
                }
            }
        }

        #pragma unroll
        for (int pp = 0; pp < 4; pp++)
            *reinterpret_cast<float2*>(so + (p0 + pp) * XC + 2 * lane) = acc[pp];
        __syncthreads();
    }
    store_out(r0 + RPB - 1);
}

extern "C" void kernel_launch(void* const* d_in, const int* in_sizes, int n_in,
                              void* d_out, int out_size)
{
    const float* x   = (const float*)d_in[0];
    const float* rot = (const float*)d_in[1];
    const float* wgt = (const float*)d_in[2];
    float* out = (float*)d_out;

    cudaFuncSetAttribute(sdw_kernel, cudaFuncAttributeMaxDynamicSharedMemorySize, SMEM_TOTAL);

    dim3 block(NTH, 1, 1);
    dim3 grid(3 * (HN / RPB), BN, CN / CPB);   // 18 x 8 x 4 = 576 blocks
    sdw_kernel<<<grid, block, SMEM_TOTAL>>>(x, rot, wgt, out);
}

// round 9
// speedup vs baseline: 2.4639x; 1.1767x over previous
#include <cuda_runtime.h>
#include <cuda_fp16.h>

// SampleDepthwise deformable depthwise conv — fp16 quad table + HFMA2 blend,
// fp16 x staging (channel-pair half2, odd-stride conflict-free smem).
// B=8, C=256, H=W=96, K=3, S=4, PAD=1.
//
// lanes = channel pairs (2 ch/lane). Per (pixel, tap): one uniform uint4 LDS
// {half2(c00,c01), half2(c10,c11), quad-byte-offset, pad}; quad weights one
// lane-contiguous LDS.128; blend = 1 HMUL2 + 3 HFMA2; g cvt once; 2 FFMA.
// x ring: half2[3][34][33] (stride 33 -> conflict-free); out staged float2.

#define BN 8
#define CN 256
#define HN 96
#define WN 96
#define HW (HN * WN)

constexpr int CPB   = 64;          // channels per block
constexpr int NPAIR = CPB / 2;     // 32 channel pairs (one per lane)
constexpr int WPB   = 32;          // pixel columns per block
constexpr int RPB   = 16;          // rows per block -> 576 blocks, single wave
constexpr int NTH   = 256;         // 8 warps, 4 px each
constexpr int XW    = WPB + 2;     // 34 staged x columns
constexpr int XCH   = NPAIR + 1;   // 33 half2 per column (odd stride, conflict-free)
constexpr int SOH   = NPAIR + 1;   // 33 float2 per out row
constexpr int NQ    = 25;          // quads: y0 in [-1,3] x x0 in [-1,3]

static __device__ __forceinline__ half2 u2h(unsigned int u) {
    half2 h;
    *reinterpret_cast<unsigned int*>(&h) = u;
    return h;
}
static __device__ __forceinline__ unsigned int h2u(half2 h) {
    return *reinterpret_cast<unsigned int*>(&h);
}

__global__ __launch_bounds__(NTH, 4)
void sdw_kernel(const float* __restrict__ x,
                const float* __restrict__ rot,
                const float* __restrict__ wgt,
                float* __restrict__ out)
{
    __shared__ __align__(16) uint4  sq[NQ * NPAIR];     // 12800 B fp16 quad table
    __shared__ __align__(16) half2  sxh[3 * XW * XCH];  // 13464 B x ring
    __shared__ __align__(16) uint4  scf[9 * WPB];       //  4608 B coef+qo
    __shared__ __align__(16) float2 so2[WPB * SOH];     //  8448 B out staging

    const int tid  = threadIdx.x;
    const int lane = tid & 31;
    const int warp = tid >> 5;

    const int b     = blockIdx.y;
    const int c0    = blockIdx.z * CPB;
    const int wbase = (blockIdx.x % 3) * WPB;
    const int r0    = (blockIdx.x / 3) * RPB;

    // ---- fp16 quad table: sq[q][pair] = {h2(w00a,w00b), ..., h2(w11a,w11b)} ----
    for (int i = tid; i < NQ * NPAIR; i += NTH) {
        const int q  = i / NPAIR;
        const int p  = i % NPAIR;
        const int y0 = q / 5 - 1;
        const int x0 = q % 5 - 1;
        const float* wa = wgt + (c0 + 2 * p) * 16;
        const float* wb = wa + 16;
        auto corner = [&](const float* wc, int y, int xq) -> float {
            return (y >= 0 && y < 4 && xq >= 0 && xq < 4) ? __ldg(wc + y * 4 + xq) : 0.f;
        };
        uint4 u;
        u.x = h2u(__floats2half2_rn(corner(wa, y0,     x0    ), corner(wb, y0,     x0    )));
        u.y = h2u(__floats2half2_rn(corner(wa, y0,     x0 + 1), corner(wb, y0,     x0 + 1)));
        u.z = h2u(__floats2half2_rn(corner(wa, y0 + 1, x0    ), corner(wb, y0 + 1, x0    )));
        u.w = h2u(__floats2half2_rn(corner(wa, y0 + 1, x0 + 1), corner(wb, y0 + 1, x0 + 1)));
        sq[i] = u;
    }

    // ---- x row staging: gmem fp32 -> smem half2 channel pairs ----
    auto load_xrow = [&](int r) {
        half2* dst = sxh + ((r + 1) % 3) * (XW * XCH);
        const bool rvalid = (unsigned)r < (unsigned)HN;
        const int  rr = rvalid ? r : 0;
        const float* src = x + (((size_t)b * CN + c0) * HN + rr) * WN + wbase;
        const int w_ = tid & 31;
        const int pb = tid >> 5;
        #pragma unroll
        for (int k = 0; k < 4; k++) {
            const int p = pb + k * 8;                       // pair 0..31
            float v0 = 0.f, v1 = 0.f;
            if (rvalid) {
                v0 = __ldg(src + (size_t)(2 * p)     * HW + w_);
                v1 = __ldg(src + (size_t)(2 * p + 1) * HW + w_);
            }
            dst[(1 + w_) * XCH + p] = __floats2half2_rn(v0, v1);
        }
        // halo columns 0 and 33
        if (tid < 64) {
            const int p    = tid >> 1;
            const int side = tid & 1;
            const int wq   = side ? 33 : 0;
            const int gw   = wbase + wq - 1;
            float v0 = 0.f, v1 = 0.f;
            if (rvalid && (unsigned)gw < (unsigned)WN) {
                const float* hp = x + (((size_t)b * CN + c0 + 2 * p) * HN + rr) * WN + gw;
                v0 = __ldg(hp);
                v1 = __ldg(hp + HW);
            }
            dst[wq * XCH + p] = __floats2half2_rn(v0, v1);
        }
    };

    constexpr float B0 = (float)(0.5 * 4.0 / 3.0 - 0.5);
    constexpr float B1 = (float)(1.5 * 4.0 / 3.0 - 0.5);
    constexpr float B2 = (float)(2.5 * 4.0 / 3.0 - 0.5);

    auto precompute = [&](int r) {
        for (int t = tid; t < 9 * WPB; t += NTH) {
            const int tap = t >> 5;
            const int px  = t & 31;
            const int kh = tap / 3, kw = tap % 3;
            const float* rp = rot + (((size_t)b * 18 + 2 * tap) * HN + r) * WN + wbase + px;
            const float ry = __ldg(rp);
            const float rx = __ldg(rp + HW);
            const float yb = (kh == 0) ? B0 : ((kh == 1) ? B1 : B2);
            const float xb = (kw == 0) ? B0 : ((kw == 1) ? B1 : B2);
            const float py = yb + ry, pxx = xb + rx;
            const float y0f = floorf(py), x0f = floorf(pxx);
            const float fy = py - y0f, fx = pxx - x0f;
            const bool vy0 = (y0f >=  0.f) && (y0f <= 3.f);
            const bool vy1 = (y0f >= -1.f) && (y0f <= 2.f);
            const bool vx0 = (x0f >=  0.f) && (x0f <= 3.f);
            const bool vx1 = (x0f >= -1.f) && (x0f <= 2.f);
            const float gy0 = 1.f - fy, gy1 = fy;
            const float gx0 = 1.f - fx, gx1 = fx;
            const float c00 = (vy0 && vx0) ? gy0 * gx0 : 0.f;
            const float c01 = (vy0 && vx1) ? gy0 * gx1 : 0.f;
            const float c10 = (vy1 && vx0) ? gy1 * gx0 : 0.f;
            const float c11 = (vy1 && vx1) ? gy1 * gx1 : 0.f;
            const int qy = (int)fminf(fmaxf(y0f, -1.f), 3.f) + 1;
            const int qx = (int)fminf(fmaxf(x0f, -1.f), 3.f) + 1;
            uint4 pc;
            pc.x = h2u(__floats2half2_rn(c00, c01));
            pc.y = h2u(__floats2half2_rn(c10, c11));
            pc.z = (unsigned)((qy * 5 + qx) * (NPAIR * 16));  // byte offset into sq
            pc.w = 0u;
            scf[t] = pc;
        }
    };

    auto store_out = [&](int rr) {
        const int w = tid & 31;
        #pragma unroll
        for (int it = 0; it < 4; it++) {
            const int p = (tid >> 5) + it * 8;              // pair 0..31
            const float2 v = so2[w * SOH + p];
            float* op = out + (((size_t)b * CN + c0 + 2 * p) * HN + rr) * WN + wbase + w;
            op[0]  = v.x;
            op[HW] = v.y;
        }
    };

    // ---- prologue ----
    load_xrow(r0 - 1);
    load_xrow(r0);

    const char* sqc = reinterpret_cast<const char*>(sq) + lane * 16;
    const int p0 = warp * 4;

    for (int r = r0; r < r0 + RPB; r++) {
        load_xrow(r + 1);
        precompute(r);
        if (r > r0) store_out(r - 1);
        __syncthreads();

        const half2* row_m1 = sxh + ( r      % 3) * (XW * XCH) + lane;
        const half2* row_0  = sxh + ((r + 1) % 3) * (XW * XCH) + lane;
        const half2* row_p1 = sxh + ((r + 2) % 3) * (XW * XCH) + lane;

        float2 acc[4];
        #pragma unroll
        for (int pp = 0; pp < 4; pp++) acc[pp] = make_float2(0.f, 0.f);

        #pragma unroll
        for (int kh = 0; kh < 3; kh++) {
            const half2* xr = (kh == 0) ? row_m1 : ((kh == 1) ? row_0 : row_p1);
            float2 xv[6];
            #pragma unroll
            for (int j = 0; j < 6; j++)
                xv[j] = __half22float2(xr[(p0 + j) * XCH]);

            #pragma unroll
            for (int kw = 0; kw < 3; kw++) {
                const uint4* cfp = scf + (kh * 3 + kw) * WPB + p0;
                #pragma unroll
                for (int pp = 0; pp < 4; pp++) {
                    const uint4 cfu = cfp[pp];                        // uniform broadcast
                    const uint4 qv  = *reinterpret_cast<const uint4*>(sqc + cfu.z);
                    const half2 cl  = u2h(cfu.x);                     // (c00, c01)
                    const half2 chh = u2h(cfu.y);                     // (c10, c11)
                    half2 g2 = __hmul2(__low2half2(cl),  u2h(qv.x));
                    g2 = __hfma2(__high2half2(cl),  u2h(qv.y), g2);
                    g2 = __hfma2(__low2half2(chh),  u2h(qv.z), g2);
                    g2 = __hfma2(__high2half2(chh), u2h(qv.w), g2);
                    const float2 g  = __half22float2(g2);
                    const float2 xx = xv[pp + kw];
                    acc[pp].x = fmaf(g.x, xx.x, acc[pp].x);
                    acc[pp].y = fmaf(g.y, xx.y, acc[pp].y);
                }
            }
        }

        #pragma unroll
        for (int pp = 0; pp < 4; pp++)
            so2[(p0 + pp) * SOH + lane] = acc[pp];
        __syncthreads();
    }
    store_out(r0 + RPB - 1);
}

extern "C" void kernel_launch(void* const* d_in, const int* in_sizes, int n_in,
                              void* d_out, int out_size)
{
    const float* x   = (const float*)d_in[0];
    const float* rot = (const float*)d_in[1];
    const float* wgt = (const float*)d_in[2];
    float* out = (float*)d_out;

    dim3 block(NTH, 1, 1);
    dim3 grid(3 * (HN / RPB), BN, CN / CPB);   // 18 x 8 x 4 = 576 blocks
    sdw_kernel<<<grid, block>>>(x, rot, wgt, out);
}